// round 2
// baseline (speedup 1.0000x reference)
#include <cuda_runtime.h>
#include <cuda_bf16.h>

// Problem constants
constexpr int B_ = 4;
constexpr int N_ = 16384;
constexpr int C_ = 128;
constexpr int M_ = 1024;
constexpr int K_ = 32;
constexpr int NCOL = B_ * M_ * K_;        // 131072
constexpr float RADIUS2 = 0.4f * 0.4f;
constexpr float EPS_ = 1e-5f;

// Scratch (device globals; no allocations allowed)
__device__ float g_X1[131 * NCOL];        // gathered + concat input (131 x NCOL)
__device__ float g_Y1[128 * NCOL];        // conv1 pre-BN output
__device__ float g_Y2[128 * NCOL];        // conv2 pre-BN output
__device__ float g_Y3[256 * NCOL];        // conv3 pre-BN output
__device__ int   g_idx[B_ * M_ * K_];     // ball query result
__device__ float g_scale[3][256];         // folded BN scale per layer
__device__ float g_shift[3][256];         // folded BN shift per layer

__device__ __forceinline__ float* bufptr(int id) {
    switch (id) {
        case 0: return g_X1;
        case 1: return g_Y1;
        case 2: return g_Y2;
        default: return g_Y3;
    }
}

// ---------------------------------------------------------------------------
// Kernel 1: ball query (one warp per query) + write new_xyz to output
// Replicates "first K indices (in index order) within radius, pad with first"
// ---------------------------------------------------------------------------
__global__ void ballquery_kernel(const float* __restrict__ xyz,
                                 const int* __restrict__ indices,
                                 float* __restrict__ out_newxyz) {
    int gwarp = (blockIdx.x * blockDim.x + threadIdx.x) >> 5;
    int lane = threadIdx.x & 31;
    int w = threadIdx.x >> 5;
    if (gwarp >= B_ * M_) return;
    int b = gwarp / M_;
    int m = gwarp % M_;

    const float* base = xyz + (size_t)b * N_ * 3;
    int center = indices[b * M_ + m];
    float qx = base[center * 3 + 0];
    float qy = base[center * 3 + 1];
    float qz = base[center * 3 + 2];
    if (lane < 3) out_newxyz[(size_t)gwarp * 3 + lane] = base[center * 3 + lane];

    __shared__ int sidx[4][K_];
    int cnt = 0;
    for (int bn = 0; bn < N_ && cnt < K_; bn += 32) {
        int n = bn + lane;
        float dx = base[n * 3 + 0] - qx;
        float dy = base[n * 3 + 1] - qy;
        float dz = base[n * 3 + 2] - qz;
        float d2 = fmaf(dx, dx, fmaf(dy, dy, dz * dz));
        bool within = d2 < RADIUS2;
        unsigned mask = __ballot_sync(0xffffffffu, within);
        int pos = cnt + __popc(mask & ((1u << lane) - 1u));
        if (within && pos < K_) sidx[w][pos] = n;
        cnt += __popc(mask);
    }
    __syncwarp();
    if (cnt > K_) cnt = K_;
    int first = (cnt > 0) ? sidx[w][0] : 0;
    if (lane < K_) {
        int v = (lane < cnt) ? sidx[w][lane] : first;
        g_idx[(size_t)gwarp * K_ + lane] = v;
    }
}

// ---------------------------------------------------------------------------
// Kernel 2: gather xyz-diff (3 rows) + features (128 rows) into X1 (131 x NCOL)
// One block per (b,m) group of K=32 columns.
// ---------------------------------------------------------------------------
__global__ void gather_kernel(const float* __restrict__ xyz,
                              const float* __restrict__ feat,
                              const float* __restrict__ newxyz) {
    int q = blockIdx.x;            // 0..B*M-1
    int b = q / M_;
    int colbase = q * K_;

    __shared__ int sid[K_];
    __shared__ float snew[3];
    if (threadIdx.x < K_) sid[threadIdx.x] = g_idx[colbase + threadIdx.x];
    if (threadIdx.x < 3) snew[threadIdx.x] = newxyz[(size_t)q * 3 + threadIdx.x];
    __syncthreads();

    int k = threadIdx.x & 31;
    int sub = threadIdx.x >> 5;    // 0..7 (256 threads)
    int n = sid[k];

    if (sub < 3) {
        g_X1[(size_t)sub * NCOL + colbase + k] =
            xyz[((size_t)b * N_ + n) * 3 + sub] - snew[sub];
    }
    const float* fb = feat + (size_t)b * C_ * N_;
    for (int c = sub; c < C_; c += 8) {
        g_X1[(size_t)(3 + c) * NCOL + colbase + k] = fb[(size_t)c * N_ + n];
    }
}

// ---------------------------------------------------------------------------
// Kernel 3: tiled GEMM  Y[Cout, NCOL] = W[Cout,Cin] * f(X[Cin,NCOL]) + bias
// f = BN(prev layer)+ReLU applied on load when APPLY (scale/shift folded).
// 64x64 block tile, BK=16, 256 threads, 4x4 per thread.
// ---------------------------------------------------------------------------
template <bool APPLY>
__global__ void __launch_bounds__(256)
gemm_kernel(const float* __restrict__ W, const float* __restrict__ bias,
            int Cout, int Cin, int xbuf, int ybuf, int in_layer) {
    constexpr int BM = 64, BN = 64, BK = 16;
    __shared__ float As[BK][BM];
    __shared__ float Bs[BK][BN];

    const float* X = bufptr(xbuf);
    float* Y = bufptr(ybuf);

    int tid = threadIdx.x;
    int tx = tid & 15;
    int ty = tid >> 4;
    int row0 = blockIdx.y * BM;
    int col0 = blockIdx.x * BN;

    float acc[4][4] = {};

    for (int kt = 0; kt < Cin; kt += BK) {
        // load A tile (64 rows x 16 k)
        #pragma unroll
        for (int i = 0; i < 4; i++) {
            int e = tid + i * 256;
            int kk = e & 15;
            int rm = e >> 4;
            int kc = kt + kk;
            As[kk][rm] = (kc < Cin) ? W[(size_t)(row0 + rm) * Cin + kc] : 0.f;
        }
        // load B tile (16 k x 64 cols), applying BN+ReLU of previous layer
        #pragma unroll
        for (int i = 0; i < 4; i++) {
            int e = tid + i * 256;
            int cn = e & 63;
            int kk = e >> 6;
            int kc = kt + kk;
            float v = 0.f;
            if (kc < Cin) {
                v = X[(size_t)kc * NCOL + col0 + cn];
                if (APPLY) {
                    v = fmaxf(fmaf(v, g_scale[in_layer][kc], g_shift[in_layer][kc]), 0.f);
                }
            }
            Bs[kk][cn] = v;
        }
        __syncthreads();

        #pragma unroll
        for (int kk = 0; kk < BK; kk++) {
            float4 av = *reinterpret_cast<const float4*>(&As[kk][ty * 4]);
            float4 bv = *reinterpret_cast<const float4*>(&Bs[kk][tx * 4]);
            float a[4] = {av.x, av.y, av.z, av.w};
            float bb[4] = {bv.x, bv.y, bv.z, bv.w};
            #pragma unroll
            for (int i = 0; i < 4; i++)
                #pragma unroll
                for (int j = 0; j < 4; j++)
                    acc[i][j] = fmaf(a[i], bb[j], acc[i][j]);
        }
        __syncthreads();
    }

    #pragma unroll
    for (int i = 0; i < 4; i++) {
        int r = row0 + ty * 4 + i;
        float bb = bias[r];
        float4 v = {acc[i][0] + bb, acc[i][1] + bb, acc[i][2] + bb, acc[i][3] + bb};
        *reinterpret_cast<float4*>(&Y[(size_t)r * NCOL + col0 + tx * 4]) = v;
    }
}

// ---------------------------------------------------------------------------
// Kernel 4: per-channel BN stats over NCOL elements -> folded scale/shift
// One block per channel; double accumulation for exactness.
// ---------------------------------------------------------------------------
__global__ void stats_kernel(int ybuf, const float* __restrict__ gamma,
                             const float* __restrict__ beta, int layer) {
    int c = blockIdx.x;
    const float* row = bufptr(ybuf) + (size_t)c * NCOL;
    double s = 0.0, s2 = 0.0;
    for (int i = threadIdx.x; i < NCOL; i += blockDim.x) {
        double v = (double)row[i];
        s += v;
        s2 += v * v;
    }
    #pragma unroll
    for (int o = 16; o > 0; o >>= 1) {
        s += __shfl_down_sync(0xffffffffu, s, o);
        s2 += __shfl_down_sync(0xffffffffu, s2, o);
    }
    __shared__ double ws[8], ws2[8];
    int w = threadIdx.x >> 5, lane = threadIdx.x & 31;
    if (lane == 0) { ws[w] = s; ws2[w] = s2; }
    __syncthreads();
    if (threadIdx.x == 0) {
        double S = 0.0, S2 = 0.0;
        #pragma unroll
        for (int i = 0; i < 8; i++) { S += ws[i]; S2 += ws2[i]; }
        double mean = S / NCOL;
        float var = (float)(S2 / NCOL - mean * mean);
        float inv = rsqrtf(var + EPS_);
        float sc = gamma[c] * inv;
        g_scale[layer][c] = sc;
        g_shift[layer][c] = beta[c] - (float)mean * sc;
    }
}

// ---------------------------------------------------------------------------
// Kernel 5: BN3 + ReLU + max over K -> new_features (B, 256, M)
// ---------------------------------------------------------------------------
__global__ void maxpool_kernel(float* __restrict__ out) {
    int idx = blockIdx.x * blockDim.x + threadIdx.x;
    if (idx >= 256 * B_ * M_) return;
    int m = idx % M_;
    int t = idx / M_;
    int c = t % 256;
    int b = t / 256;

    float sc = g_scale[2][c];
    float sh = g_shift[2][c];
    const float* row = g_Y3 + (size_t)c * NCOL + ((size_t)b * M_ + m) * K_;
    float mx = 0.f;   // ReLU lower-bounds values at 0
    #pragma unroll
    for (int k = 0; k < K_; k += 4) {
        float4 v = *reinterpret_cast<const float4*>(&row[k]);
        mx = fmaxf(mx, fmaf(v.x, sc, sh));
        mx = fmaxf(mx, fmaf(v.y, sc, sh));
        mx = fmaxf(mx, fmaf(v.z, sc, sh));
        mx = fmaxf(mx, fmaf(v.w, sc, sh));
    }
    out[12288 + ((size_t)b * 256 + c) * M_ + m] = mx;
}

// ---------------------------------------------------------------------------
extern "C" void kernel_launch(void* const* d_in, const int* in_sizes, int n_in,
                              void* d_out, int out_size) {
    const float* xyz  = (const float*)d_in[0];
    const float* feat = (const float*)d_in[1];
    const int* indices = (const int*)d_in[2];
    const float* w1 = (const float*)d_in[3];
    const float* b1 = (const float*)d_in[4];
    const float* g1 = (const float*)d_in[5];
    const float* be1 = (const float*)d_in[6];
    const float* w2 = (const float*)d_in[7];
    const float* b2 = (const float*)d_in[8];
    const float* g2 = (const float*)d_in[9];
    const float* be2 = (const float*)d_in[10];
    const float* w3 = (const float*)d_in[11];
    const float* b3 = (const float*)d_in[12];
    const float* g3 = (const float*)d_in[13];
    const float* be3 = (const float*)d_in[14];
    float* out = (float*)d_out;

    // 1. ball query + new_xyz
    ballquery_kernel<<<(B_ * M_) / 4, 128>>>(xyz, indices, out);
    // 2. gather + concat into X1
    gather_kernel<<<B_ * M_, 256>>>(xyz, feat, out);
    // 3. conv1 (131 -> 128), raw input
    gemm_kernel<false><<<dim3(NCOL / 64, 128 / 64), 256>>>(w1, b1, 128, 131, 0, 1, 0);
    stats_kernel<<<128, 256>>>(1, g1, be1, 0);
    // 4. conv2 (128 -> 128), BN1+ReLU applied on load
    gemm_kernel<true><<<dim3(NCOL / 64, 128 / 64), 256>>>(w2, b2, 128, 128, 1, 2, 0);
    stats_kernel<<<128, 256>>>(2, g2, be2, 1);
    // 5. conv3 (128 -> 256), BN2+ReLU applied on load
    gemm_kernel<true><<<dim3(NCOL / 64, 256 / 64), 256>>>(w3, b3, 256, 128, 2, 3, 1);
    stats_kernel<<<256, 256>>>(3, g3, be3, 2);
    // 6. BN3 + ReLU + max over K
    maxpool_kernel<<<(256 * B_ * M_) / 256, 256>>>(out);
}

// round 3
// speedup vs baseline: 2.8221x; 2.8221x over previous
#include <cuda_runtime.h>
#include <cuda_bf16.h>

constexpr int B_ = 4;
constexpr int N_ = 16384;
constexpr int C_ = 128;
constexpr int M_ = 1024;
constexpr int K_ = 32;
constexpr int NCOL = B_ * M_ * K_;        // 131072
constexpr int NCB = NCOL / 128;           // 1024 column blocks
constexpr float RADIUS2 = 0.4f * 0.4f;
constexpr float EPS_ = 1e-5f;

// Scratch (device globals; no allocations allowed)
__device__ float g_X1[131 * NCOL];
__device__ float g_Y1[128 * NCOL];
__device__ float g_Y2[128 * NCOL];
__device__ float g_Y3[256 * NCOL];
__device__ int   g_idx[B_ * M_ * K_];
__device__ float g_scale[3][256];
__device__ float g_shift[3][256];
__device__ float g_psum[256][NCB];
__device__ float g_psum2[256][NCB];

__device__ __forceinline__ float* bufptr(int id) {
    switch (id) {
        case 0: return g_X1;
        case 1: return g_Y1;
        case 2: return g_Y2;
        default: return g_Y3;
    }
}

// ---------------------------------------------------------------------------
// Kernel 1: ball query (one warp per query) + write new_xyz to output
// ---------------------------------------------------------------------------
__global__ void ballquery_kernel(const float* __restrict__ xyz,
                                 const int* __restrict__ indices,
                                 float* __restrict__ out_newxyz) {
    int gwarp = (blockIdx.x * blockDim.x + threadIdx.x) >> 5;
    int lane = threadIdx.x & 31;
    int w = threadIdx.x >> 5;
    if (gwarp >= B_ * M_) return;
    int b = gwarp / M_;
    int m = gwarp % M_;

    const float* base = xyz + (size_t)b * N_ * 3;
    int center = indices[b * M_ + m];
    float qx = base[center * 3 + 0];
    float qy = base[center * 3 + 1];
    float qz = base[center * 3 + 2];
    if (lane < 3) out_newxyz[(size_t)gwarp * 3 + lane] = base[center * 3 + lane];

    __shared__ int sidx[4][K_];
    int cnt = 0;
    for (int bn = 0; bn < N_ && cnt < K_; bn += 32) {
        int n = bn + lane;
        float dx = base[n * 3 + 0] - qx;
        float dy = base[n * 3 + 1] - qy;
        float dz = base[n * 3 + 2] - qz;
        float d2 = fmaf(dx, dx, fmaf(dy, dy, dz * dz));
        bool within = d2 < RADIUS2;
        unsigned mask = __ballot_sync(0xffffffffu, within);
        int pos = cnt + __popc(mask & ((1u << lane) - 1u));
        if (within && pos < K_) sidx[w][pos] = n;
        cnt += __popc(mask);
    }
    __syncwarp();
    if (cnt > K_) cnt = K_;
    int first = (cnt > 0) ? sidx[w][0] : 0;
    if (lane < K_) {
        int v = (lane < cnt) ? sidx[w][lane] : first;
        g_idx[(size_t)gwarp * K_ + lane] = v;
    }
}

// ---------------------------------------------------------------------------
// Kernel 2: gather xyz-diff (3 rows) + features (128 rows) into X1 (131 x NCOL)
// ---------------------------------------------------------------------------
__global__ void gather_kernel(const float* __restrict__ xyz,
                              const float* __restrict__ feat,
                              const float* __restrict__ newxyz) {
    int q = blockIdx.x;            // 0..B*M-1
    int b = q / M_;
    int colbase = q * K_;

    __shared__ int sid[K_];
    __shared__ float snew[3];
    if (threadIdx.x < K_) sid[threadIdx.x] = g_idx[colbase + threadIdx.x];
    if (threadIdx.x < 3) snew[threadIdx.x] = newxyz[(size_t)q * 3 + threadIdx.x];
    __syncthreads();

    int k = threadIdx.x & 31;
    int sub = threadIdx.x >> 5;    // 0..7 (256 threads)
    int n = sid[k];

    if (sub < 3) {
        g_X1[(size_t)sub * NCOL + colbase + k] =
            xyz[((size_t)b * N_ + n) * 3 + sub] - snew[sub];
    }
    const float* fb = feat + (size_t)b * C_ * N_;
    for (int c = sub; c < C_; c += 8) {
        g_X1[(size_t)(3 + c) * NCOL + colbase + k] = fb[(size_t)c * N_ + n];
    }
}

// ---------------------------------------------------------------------------
// Kernel 3: 128x128x16 double-buffered GEMM + fused per-row stats partials
//   Y[Cout, NCOL] = W[Cout,Cin] * f(X[Cin,NCOL]) + bias
//   f = BN(prev)+ReLU folded on load when APPLY.
//   Also writes per-(row, colblock) sum / sumsq partials (deterministic).
// ---------------------------------------------------------------------------
template <bool APPLY>
__global__ void __launch_bounds__(256)
gemm_kernel(const float* __restrict__ W, const float* __restrict__ bias,
            int Cin, int xbuf, int ybuf, int layer_in) {
    constexpr int BM = 128, BN = 128, BK = 16;
    __shared__ float Asm[2][BM][BK + 1];   // [rm][kk], padded
    __shared__ float Bsm[2][BK][BN];

    const float* X = bufptr(xbuf);
    float* Y = bufptr(ybuf);

    int tid = threadIdx.x;
    int tx = tid & 15;
    int ty = tid >> 4;
    int col0 = blockIdx.x * BN;
    int row0 = blockIdx.y * BM;
    int ntiles = (Cin + BK - 1) / BK;

    float a_reg[8];
    float4 b_reg[2];

    // ---- global loads (to registers) for tile t ----
    auto loadA = [&](int t) {
        int kt = t * BK;
        #pragma unroll
        for (int i = 0; i < 8; i++) {
            int e = tid + i * 256;
            int kk = e & 15;
            int rm = e >> 4;
            int kc = kt + kk;
            a_reg[i] = (kc < Cin) ? W[(size_t)(row0 + rm) * Cin + kc] : 0.f;
        }
    };
    auto loadB = [&](int t) {
        int kt = t * BK;
        #pragma unroll
        for (int i = 0; i < 2; i++) {
            int f = tid + i * 256;
            int c4 = f & 31;
            int kk = f >> 5;
            int kc = kt + kk;
            if (kc < Cin) {
                float4 v = *reinterpret_cast<const float4*>(
                    &X[(size_t)kc * NCOL + col0 + c4 * 4]);
                if (APPLY) {
                    float sc = g_scale[layer_in][kc];
                    float sh = g_shift[layer_in][kc];
                    v.x = fmaxf(fmaf(v.x, sc, sh), 0.f);
                    v.y = fmaxf(fmaf(v.y, sc, sh), 0.f);
                    v.z = fmaxf(fmaf(v.z, sc, sh), 0.f);
                    v.w = fmaxf(fmaf(v.w, sc, sh), 0.f);
                }
                b_reg[i] = v;
            } else {
                b_reg[i] = make_float4(0.f, 0.f, 0.f, 0.f);
            }
        }
    };
    auto storeA = [&](int buf) {
        #pragma unroll
        for (int i = 0; i < 8; i++) {
            int e = tid + i * 256;
            int kk = e & 15;
            int rm = e >> 4;
            Asm[buf][rm][kk] = a_reg[i];
        }
    };
    auto storeB = [&](int buf) {
        #pragma unroll
        for (int i = 0; i < 2; i++) {
            int f = tid + i * 256;
            int c4 = f & 31;
            int kk = f >> 5;
            *reinterpret_cast<float4*>(&Bsm[buf][kk][c4 * 4]) = b_reg[i];
        }
    };

    float acc[8][8] = {};   // rows: ri*4+i (ri in {0,1}: +0/+64); cols: cj*4+j

    loadA(0); loadB(0);
    storeA(0); storeB(0);
    __syncthreads();

    int buf = 0;
    for (int t = 0; t < ntiles; t++) {
        if (t + 1 < ntiles) { loadA(t + 1); loadB(t + 1); }
        #pragma unroll
        for (int kk = 0; kk < BK; kk++) {
            float a[8], b[8];
            #pragma unroll
            for (int i = 0; i < 4; i++) {
                a[i]     = Asm[buf][ty * 4 + i][kk];
                a[4 + i] = Asm[buf][64 + ty * 4 + i][kk];
            }
            float4 bv0 = *reinterpret_cast<const float4*>(&Bsm[buf][kk][tx * 4]);
            float4 bv1 = *reinterpret_cast<const float4*>(&Bsm[buf][kk][64 + tx * 4]);
            b[0] = bv0.x; b[1] = bv0.y; b[2] = bv0.z; b[3] = bv0.w;
            b[4] = bv1.x; b[5] = bv1.y; b[6] = bv1.z; b[7] = bv1.w;
            #pragma unroll
            for (int u = 0; u < 8; u++)
                #pragma unroll
                for (int v = 0; v < 8; v++)
                    acc[u][v] = fmaf(a[u], b[v], acc[u][v]);
        }
        if (t + 1 < ntiles) { storeA(buf ^ 1); storeB(buf ^ 1); }
        __syncthreads();
        buf ^= 1;
    }

    // ---- epilogue: write Y (+bias) and per-row stats partials ----
    float rs[8], rq[8];
    #pragma unroll
    for (int u = 0; u < 8; u++) {
        int ri = u >> 2, i = u & 3;
        int r = row0 + ri * 64 + ty * 4 + i;
        float bb = bias[r];
        float4 v0 = {acc[u][0] + bb, acc[u][1] + bb, acc[u][2] + bb, acc[u][3] + bb};
        float4 v1 = {acc[u][4] + bb, acc[u][5] + bb, acc[u][6] + bb, acc[u][7] + bb};
        *reinterpret_cast<float4*>(&Y[(size_t)r * NCOL + col0 + tx * 4]) = v0;
        *reinterpret_cast<float4*>(&Y[(size_t)r * NCOL + col0 + 64 + tx * 4]) = v1;
        float s = v0.x + v0.y + v0.z + v0.w + v1.x + v1.y + v1.z + v1.w;
        float q = v0.x * v0.x + v0.y * v0.y + v0.z * v0.z + v0.w * v0.w
                + v1.x * v1.x + v1.y * v1.y + v1.z * v1.z + v1.w * v1.w;
        rs[u] = s; rq[u] = q;
    }
    // reduce across tx (16 lanes; lanes [0..15] and [16..31] are distinct ty)
    #pragma unroll
    for (int mask = 8; mask > 0; mask >>= 1) {
        #pragma unroll
        for (int u = 0; u < 8; u++) {
            rs[u] += __shfl_xor_sync(0xffffffffu, rs[u], mask);
            rq[u] += __shfl_xor_sync(0xffffffffu, rq[u], mask);
        }
    }
    if (tx == 0) {
        #pragma unroll
        for (int u = 0; u < 8; u++) {
            int ri = u >> 2, i = u & 3;
            int r = row0 + ri * 64 + ty * 4 + i;
            g_psum[r][blockIdx.x] = rs[u];
            g_psum2[r][blockIdx.x] = rq[u];
        }
    }
}

// ---------------------------------------------------------------------------
// Kernel 4: finalize BN stats from partials -> folded scale/shift
// ---------------------------------------------------------------------------
__global__ void finalize_kernel(const float* __restrict__ gamma,
                                const float* __restrict__ beta, int layer) {
    int c = blockIdx.x;
    double s = 0.0, s2 = 0.0;
    for (int j = threadIdx.x; j < NCB; j += 256) {
        s += (double)g_psum[c][j];
        s2 += (double)g_psum2[c][j];
    }
    #pragma unroll
    for (int o = 16; o > 0; o >>= 1) {
        s += __shfl_down_sync(0xffffffffu, s, o);
        s2 += __shfl_down_sync(0xffffffffu, s2, o);
    }
    __shared__ double ws[8], ws2[8];
    int w = threadIdx.x >> 5, lane = threadIdx.x & 31;
    if (lane == 0) { ws[w] = s; ws2[w] = s2; }
    __syncthreads();
    if (threadIdx.x == 0) {
        double S = 0.0, S2 = 0.0;
        #pragma unroll
        for (int i = 0; i < 8; i++) { S += ws[i]; S2 += ws2[i]; }
        double mean = S / NCOL;
        float var = (float)(S2 / NCOL - mean * mean);
        float inv = rsqrtf(var + EPS_);
        float sc = gamma[c] * inv;
        g_scale[layer][c] = sc;
        g_shift[layer][c] = beta[c] - (float)mean * sc;
    }
}

// ---------------------------------------------------------------------------
// Kernel 5: BN3 + ReLU + max over K -> new_features (B, 256, M)
// ---------------------------------------------------------------------------
__global__ void maxpool_kernel(float* __restrict__ out) {
    int idx = blockIdx.x * blockDim.x + threadIdx.x;
    if (idx >= 256 * B_ * M_) return;
    int m = idx % M_;
    int t = idx / M_;
    int c = t % 256;
    int b = t / 256;

    float sc = g_scale[2][c];
    float sh = g_shift[2][c];
    const float* row = g_Y3 + (size_t)c * NCOL + ((size_t)b * M_ + m) * K_;
    float mx = 0.f;
    #pragma unroll
    for (int k = 0; k < K_; k += 4) {
        float4 v = *reinterpret_cast<const float4*>(&row[k]);
        mx = fmaxf(mx, fmaf(v.x, sc, sh));
        mx = fmaxf(mx, fmaf(v.y, sc, sh));
        mx = fmaxf(mx, fmaf(v.z, sc, sh));
        mx = fmaxf(mx, fmaf(v.w, sc, sh));
    }
    out[12288 + ((size_t)b * 256 + c) * M_ + m] = mx;
}

// ---------------------------------------------------------------------------
extern "C" void kernel_launch(void* const* d_in, const int* in_sizes, int n_in,
                              void* d_out, int out_size) {
    const float* xyz  = (const float*)d_in[0];
    const float* feat = (const float*)d_in[1];
    const int* indices = (const int*)d_in[2];
    const float* w1 = (const float*)d_in[3];
    const float* b1 = (const float*)d_in[4];
    const float* g1 = (const float*)d_in[5];
    const float* be1 = (const float*)d_in[6];
    const float* w2 = (const float*)d_in[7];
    const float* b2 = (const float*)d_in[8];
    const float* g2 = (const float*)d_in[9];
    const float* be2 = (const float*)d_in[10];
    const float* w3 = (const float*)d_in[11];
    const float* b3 = (const float*)d_in[12];
    const float* g3 = (const float*)d_in[13];
    const float* be3 = (const float*)d_in[14];
    float* out = (float*)d_out;

    ballquery_kernel<<<(B_ * M_) / 4, 128>>>(xyz, indices, out);
    gather_kernel<<<B_ * M_, 256>>>(xyz, feat, out);

    // conv1: 131 -> 128 (raw input)
    gemm_kernel<false><<<dim3(NCB, 1), 256>>>(w1, b1, 131, 0, 1, 0);
    finalize_kernel<<<128, 256>>>(g1, be1, 0);
    // conv2: 128 -> 128 (BN1+ReLU on load)
    gemm_kernel<true><<<dim3(NCB, 1), 256>>>(w2, b2, 128, 1, 2, 0);
    finalize_kernel<<<128, 256>>>(g2, be2, 1);
    // conv3: 128 -> 256 (BN2+ReLU on load)
    gemm_kernel<true><<<dim3(NCB, 2), 256>>>(w3, b3, 128, 2, 3, 1);
    finalize_kernel<<<256, 256>>>(g3, be3, 2);
    // BN3 + ReLU + max over K
    maxpool_kernel<<<(256 * B_ * M_) / 256, 256>>>(out);
}